// round 14
// baseline (speedup 1.0000x reference)
#include <cuda_runtime.h>
#include <mma.h>
#include <cuda_fp16.h>
#include <cstdint>
#include <cstddef>

using namespace nvcuda;

namespace cfg {
constexpr int B = 16, S = 512, D = 768, H = 12, DH = 64, L = 12, FF = 3072, V = 30522;
constexpr int T = B * S;          // 8192 tokens
constexpr int QN = 3 * D;         // 2304 (q|k|v packed)
}

// -------------------- scratch (static device memory; no allocs) --------------------
__device__ float  g_x[(size_t)cfg::T * cfg::D];              // residual (fp32)
__device__ __half g_h[(size_t)cfg::T * cfg::D];              // LN out (half)
__device__ __half g_qkv[(size_t)cfg::T * cfg::QN];           // q|k|v (half)
__device__ __half g_o[(size_t)cfg::T * cfg::D];              // attn out (half)
__device__ __half g_ff[(size_t)cfg::T * cfg::FF];            // FFN hidden (half)
__device__ __half g_wqkv[(size_t)cfg::L * cfg::D * cfg::QN]; // packed qkv W (half)
__device__ __half g_wo[(size_t)cfg::L * cfg::D * cfg::D];
__device__ __half g_w1[(size_t)cfg::L * cfg::D * cfg::FF];
__device__ __half g_w2[(size_t)cfg::L * cfg::FF * cfg::D];
__device__ int g_idx64;

// -------------------- idx dtype probe --------------------
__global__ void detect_idx_kernel(const void* p) {
    const long long* q = (const long long*)p;
    __shared__ int sbad;
    if (threadIdx.x == 0) sbad = 0;
    __syncthreads();
    int bad = 0;
    for (int i = threadIdx.x; i < 4096; i += 256) {
        long long v = q[i];
        if (v < 0 || v >= (long long)cfg::V) bad = 1;
    }
    if (bad) atomicOr(&sbad, 1);
    __syncthreads();
    if (threadIdx.x == 0) g_idx64 = sbad ? 0 : 1;
}

// -------------------- weight repack: (L,H,D,DH)x3 -> (L, D, 2304) half -------------
__global__ void repack_kernel(const float* __restrict__ Wq,
                              const float* __restrict__ Wk,
                              const float* __restrict__ Wv) {
    size_t i = (size_t)blockIdx.x * blockDim.x + threadIdx.x;
    size_t total = (size_t)cfg::L * cfg::D * cfg::QN;
    if (i >= total) return;
    int j = (int)(i % cfg::QN);
    size_t ld = i / cfg::QN;
    int d = (int)(ld % cfg::D);
    int l = (int)(ld / cfg::D);
    const float* W;
    int jj = j;
    if (j < cfg::D) { W = Wq; }
    else if (j < 2 * cfg::D) { W = Wk; jj = j - cfg::D; }
    else { W = Wv; jj = j - 2 * cfg::D; }
    int h = jj / cfg::DH, k = jj % cfg::DH;
    g_wqkv[i] = __float2half_rn(W[((((size_t)l * cfg::H + h) * cfg::D) + d) * cfg::DH + k]);
}

// -------------------- merged half convert of Wo, W1, W2 --------------------
__global__ void prep_weights_kernel(const float* __restrict__ Wo,
                                    const float* __restrict__ W1,
                                    const float* __restrict__ W2) {
    using namespace cfg;
    constexpr size_t N1 = (size_t)L * D * D / 4;
    constexpr size_t N2 = N1 + (size_t)L * D * FF / 4;
    constexpr size_t N3 = N2 + (size_t)L * FF * D / 4;
    size_t i = (size_t)blockIdx.x * blockDim.x + threadIdx.x;
    if (i >= N3) return;
    const float4* src;
    __half* dst;
    size_t off;
    if (i < N1)      { src = (const float4*)Wo; dst = g_wo; off = i; }
    else if (i < N2) { src = (const float4*)W1; dst = g_w1; off = i - N1; }
    else             { src = (const float4*)W2; dst = g_w2; off = i - N2; }
    float4 v = src[off];
    __half2 h0 = __floats2half2_rn(v.x, v.y);
    __half2 h1 = __floats2half2_rn(v.z, v.w);
    uint2 u;
    u.x = reinterpret_cast<uint32_t&>(h0);
    u.y = reinterpret_cast<uint32_t&>(h1);
    *reinterpret_cast<uint2*>(dst + off * 4) = u;
}

// -------------------- block reduction helper (256 threads) --------------------
__device__ __forceinline__ float block_sum256(float v, float* red) {
    int lane = threadIdx.x & 31, warp = threadIdx.x >> 5;
#pragma unroll
    for (int o = 16; o; o >>= 1) v += __shfl_xor_sync(0xffffffffu, v, o);
    if (lane == 0) red[warp] = v;
    __syncthreads();
    if (threadIdx.x == 0) {
        float s = 0.f;
#pragma unroll
        for (int i = 0; i < 8; i++) s += red[i];
        red[8] = s;
    }
    __syncthreads();
    float r = red[8];
    __syncthreads();
    return r;
}

// -------------------- fused embedding + LN_emb + LN1(layer0) --------------------
__global__ void embed_ln_ln1_kernel(const void* __restrict__ idxp,
                                    const float* __restrict__ tok,
                                    const float* __restrict__ seg,
                                    const float* __restrict__ pos,
                                    const float* __restrict__ ge, const float* __restrict__ be,
                                    const float* __restrict__ g1, const float* __restrict__ b1) {
    __shared__ float red[9];
    int t = blockIdx.x;
    int s = t % cfg::S;
    long long id;
    if (g_idx64) id = ((const long long*)idxp)[t];
    else         id = (long long)((const int*)idxp)[t];
    int sg = (s >= cfg::S / 2 + 1) ? 1 : 0;
    float v[3];
#pragma unroll
    for (int i = 0; i < 3; i++) {
        int c = threadIdx.x + i * 256;
        v[i] = tok[(size_t)id * cfg::D + c] + seg[(size_t)sg * cfg::D + c] + pos[(size_t)s * cfg::D + c];
    }
    float mean = block_sum256(v[0] + v[1] + v[2], red) * (1.f / cfg::D);
    float q = 0.f;
#pragma unroll
    for (int i = 0; i < 3; i++) { float d = v[i] - mean; q += d * d; }
    float var = block_sum256(q, red) * (1.f / cfg::D);
    float inv = rsqrtf(var + 1e-5f);
    float x[3];
#pragma unroll
    for (int i = 0; i < 3; i++) {
        int c = threadIdx.x + i * 256;
        x[i] = (v[i] - mean) * inv * ge[c] + be[c];
        g_x[(size_t)t * cfg::D + c] = x[i];
    }
    float mean2 = block_sum256(x[0] + x[1] + x[2], red) * (1.f / cfg::D);
    float q2 = 0.f;
#pragma unroll
    for (int i = 0; i < 3; i++) { float d = x[i] - mean2; q2 += d * d; }
    float var2 = block_sum256(q2, red) * (1.f / cfg::D);
    float inv2 = rsqrtf(var2 + 1e-5f);
#pragma unroll
    for (int i = 0; i < 3; i++) {
        int c = threadIdx.x + i * 256;
        g_h[(size_t)t * cfg::D + c] = __float2half_rn((x[i] - mean2) * inv2 * g1[c] + b1[c]);
    }
}

// -------------------- LayerNorm to half (GEMM operand) --------------------
__global__ void ln_half_kernel(const float* __restrict__ src, __half* __restrict__ dst,
                               const float* __restrict__ g, const float* __restrict__ b) {
    __shared__ float red[9];
    int t = blockIdx.x;
    const float* x = src + (size_t)t * cfg::D;
    float v[3];
#pragma unroll
    for (int i = 0; i < 3; i++) v[i] = x[threadIdx.x + i * 256];
    float mean = block_sum256(v[0] + v[1] + v[2], red) * (1.f / cfg::D);
    float q = 0.f;
#pragma unroll
    for (int i = 0; i < 3; i++) { float d = v[i] - mean; q += d * d; }
    float var = block_sum256(q, red) * (1.f / cfg::D);
    float inv = rsqrtf(var + 1e-5f);
#pragma unroll
    for (int i = 0; i < 3; i++) {
        int c = threadIdx.x + i * 256;
        dst[(size_t)t * cfg::D + c] = __float2half_rn((v[i] - mean) * inv * g[c] + b[c]);
    }
}

// -------------------- final LayerNorm to fp32 --------------------
__global__ void ln_float_kernel(const float* __restrict__ src, float* __restrict__ dst,
                                const float* __restrict__ g, const float* __restrict__ b) {
    __shared__ float red[9];
    int t = blockIdx.x;
    const float* x = src + (size_t)t * cfg::D;
    float v[3];
#pragma unroll
    for (int i = 0; i < 3; i++) v[i] = x[threadIdx.x + i * 256];
    float mean = block_sum256(v[0] + v[1] + v[2], red) * (1.f / cfg::D);
    float q = 0.f;
#pragma unroll
    for (int i = 0; i < 3; i++) { float d = v[i] - mean; q += d * d; }
    float var = block_sum256(q, red) * (1.f / cfg::D);
    float inv = rsqrtf(var + 1e-5f);
#pragma unroll
    for (int i = 0; i < 3; i++) {
        int c = threadIdx.x + i * 256;
        dst[(size_t)t * cfg::D + c] = (v[i] - mean) * inv * g[c] + b[c];
    }
}

// -------------------- cp.async helpers --------------------
__device__ __forceinline__ void cpasync16(void* smem, const void* gmem) {
    uint32_t s = (uint32_t)__cvta_generic_to_shared(smem);
    asm volatile("cp.async.cg.shared.global [%0], [%1], 16;\n" :: "r"(s), "l"(gmem));
}
__device__ __forceinline__ void cp_commit() {
    asm volatile("cp.async.commit_group;\n");
}

// -------------------- pipelined fp16 WMMA GEMM, warp tile 64x64, BK=64 -------------
// 3-stage ring, ONE __syncthreads per k-iteration, wait_group 1.
// A group is committed every iteration (possibly empty) so wait_group 1 retires
// exactly the tile needed this iteration even in the drain phase.
// C[M,N] = A[M,K] @ B[K,N]; A,B half row-major; accum fp32.
// 128 threads (2x2 warps), block 128x128.
// EPI: 0 = store half, 1 = float C = res + AB + bias, 2 = half C = relu(AB + bias)
namespace gk {
constexpr int BM = 128, BN = 128, BK = 64, STG = 3;
constexpr int ASTR = 72;                   // halfs (64 + 8 pad)
constexpr int BSTR = 136;                  // halfs (128 + 8 pad)
constexpr int A_TILE = BM * ASTR;          // 9216 halfs
constexpr int B_TILE = BK * BSTR;          // 8704 halfs
constexpr int STAGE_H = A_TILE + B_TILE;   // 17920 halfs (35840 B)
constexpr int ESTR = 132;                  // fp32 epilogue stride
constexpr int SMEM_BYTES = STG * STAGE_H * 2;  // 107520 (covers epilogue 67584)
}

template <int EPI, typename OutT>
__global__ __launch_bounds__(128, 2)
void gemm_fp16(const __half* __restrict__ A, const __half* __restrict__ B,
               OutT* __restrict__ C, const float* __restrict__ bias,
               const float* __restrict__ res, int M, int N, int K) {
    using namespace gk;
    extern __shared__ char smc[];
    __half* sm = reinterpret_cast<__half*>(smc);

    const int tid = threadIdx.x, warp = tid >> 5;
    const int wy = warp >> 1, wx = warp & 1;     // 2x2 warps, warp tile 64x64
    const int bm = blockIdx.y * BM, bn = blockIdx.x * BN;

    wmma::fragment<wmma::accumulator, 16, 16, 16, float> acc[4][4];
#pragma unroll
    for (int i = 0; i < 4; i++)
#pragma unroll
        for (int j = 0; j < 4; j++) wmma::fill_fragment(acc[i][j], 0.f);

    auto load_tiles = [&](int st, int kt) {
        __half* dstA = sm + st * STAGE_H;
        const __half* srcA = A + (size_t)bm * K + kt * BK;
#pragma unroll
        for (int i = 0; i < 8; i++) {                 // 128 rows x 8 chunks of 8 halfs
            int id = tid + i * 128;
            int r = id >> 3, c = (id & 7) * 8;
            cpasync16(&dstA[r * ASTR + c], &srcA[(size_t)r * K + c]);
        }
        __half* dstB = sm + st * STAGE_H + A_TILE;
        const __half* srcB = B + (size_t)(kt * BK) * N + bn;
#pragma unroll
        for (int i = 0; i < 8; i++) {                 // 64 rows x 16 chunks
            int id = tid + i * 128;
            int r = id >> 4, c = (id & 15) * 8;
            cpasync16(&dstB[r * BSTR + c], &srcB[(size_t)r * N + c]);
        }
    };

    const int nk = K / BK;                // 12 or 48 (always >= 2)
    load_tiles(0, 0); cp_commit();
    load_tiles(1, 1); cp_commit();

    for (int kt = 0; kt < nk; kt++) {
        asm volatile("cp.async.wait_group 1;\n");   // retires group kt exactly
        __syncthreads();                            // kt ready; prev compute done
        // prefetch kt+2 into stage (kt+2)%3 (= stage (kt-1)%3, fenced above)
        if (kt + 2 < nk) load_tiles((kt + 2) % STG, kt + 2);
        cp_commit();                                // commit even if empty

        const __half* a = sm + (kt % STG) * STAGE_H;
        const __half* b = a + A_TILE;
#pragma unroll
        for (int kk = 0; kk < BK; kk += 16) {
            wmma::fragment<wmma::matrix_a, 16, 16, 16, __half, wmma::row_major> af[4];
            wmma::fragment<wmma::matrix_b, 16, 16, 16, __half, wmma::row_major> bf[4];
#pragma unroll
            for (int i = 0; i < 4; i++)
                wmma::load_matrix_sync(af[i], a + (wy * 64 + i * 16) * ASTR + kk, ASTR);
#pragma unroll
            for (int j = 0; j < 4; j++)
                wmma::load_matrix_sync(bf[j], b + kk * BSTR + wx * 64 + j * 16, BSTR);
#pragma unroll
            for (int i = 0; i < 4; i++)
#pragma unroll
                for (int j = 0; j < 4; j++)
                    wmma::mma_sync(acc[i][j], af[i], bf[j], acc[i][j]);
        }
    }
    __syncthreads();   // all compute done before smem reuse as epilogue buffer

    // epilogue: stage fp32 128x128 in smem, fused write
    float* epi = reinterpret_cast<float*>(smc);
#pragma unroll
    for (int i = 0; i < 4; i++)
#pragma unroll
        for (int j = 0; j < 4; j++)
            wmma::store_matrix_sync(epi + (wy * 64 + i * 16) * ESTR + wx * 64 + j * 16,
                                    acc[i][j], ESTR, wmma::mem_row_major);
    __syncthreads();
#pragma unroll
    for (int it = 0; it < 32; it++) {
        int id = tid + it * 128;
        int r = id >> 5, c4 = (id & 31) * 4;
        float4 v = *reinterpret_cast<float4*>(&epi[r * ESTR + c4]);
        int gc = bn + c4;
        size_t gi = (size_t)(bm + r) * N + gc;
        if (EPI == 1) {
            float4 rv = *reinterpret_cast<const float4*>(&res[gi]);
            float4 bv = *reinterpret_cast<const float4*>(&bias[gc]);
            v.x += rv.x + bv.x; v.y += rv.y + bv.y; v.z += rv.z + bv.z; v.w += rv.w + bv.w;
            *reinterpret_cast<float4*>(&((float*)C)[gi]) = v;
        } else {
            if (EPI == 2) {
                float4 bv = *reinterpret_cast<const float4*>(&bias[gc]);
                v.x = fmaxf(v.x + bv.x, 0.f); v.y = fmaxf(v.y + bv.y, 0.f);
                v.z = fmaxf(v.z + bv.z, 0.f); v.w = fmaxf(v.w + bv.w, 0.f);
            }
            __half2 h0 = __floats2half2_rn(v.x, v.y);
            __half2 h1 = __floats2half2_rn(v.z, v.w);
            uint2 u;
            u.x = reinterpret_cast<uint32_t&>(h0);
            u.y = reinterpret_cast<uint32_t&>(h1);
            *reinterpret_cast<uint2*>(&((__half*)C)[gi]) = u;
        }
    }
}

// -------------------- fp16 WMMA flash attention, register O accumulator ------------
// grid (S/64, H, B), 256 threads (8 warps as 4x2; warp tile 16x32).
namespace ak {
constexpr int STRH = 72;                       // half tile stride
constexpr int STRF = 68;                       // fp32 stride
constexpr int TILEB = 64 * STRH * 2;           // 9216 B per half tile
constexpr int QH_OFF = 0;
constexpr int KH_OFF = QH_OFF + TILEB;         // K0, K1
constexpr int VH_OFF = KH_OFF + 2 * TILEB;     // V0, V1
constexpr int PH_OFF = VH_OFF + 2 * TILEB;     // half P tile
constexpr int SF_OFF = PH_OFF + TILEB;         // fp32 scores / PV result (reused)
constexpr int SMEM_BYTES = SF_OFF + 64 * STRF * 4;  // 72704
}

__global__ __launch_bounds__(256)
void attn_kernel() {
    using namespace ak;
    extern __shared__ char smc[];
    __half* Qs = reinterpret_cast<__half*>(smc + QH_OFF);
    __half* Ph = reinterpret_cast<__half*>(smc + PH_OFF);
    float*  Sf = reinterpret_cast<float*>(smc + SF_OFF);

    const int qb = blockIdx.x, h = blockIdx.y, b = blockIdx.z;
    const int tid = threadIdx.x, warp = tid >> 5;
    const int wy = warp >> 1, wx = warp & 1;
    const int r = tid >> 2, q4 = tid & 3;
    const size_t tokbase = (size_t)b * cfg::S;

    auto load_kv = [&](int st, int ck) {
        __half* Kd = reinterpret_cast<__half*>(smc + KH_OFF + st * TILEB);
        __half* Vd = reinterpret_cast<__half*>(smc + VH_OFF + st * TILEB);
#pragma unroll
        for (int i = 0; i < 2; i++) {
            int id = tid + i * 256;                  // 512 chunks of 8 halfs
            int rr = id >> 3, cc = (id & 7) * 8;
            size_t base = (tokbase + ck * 64 + rr) * cfg::QN + h * cfg::DH + cc;
            cpasync16(&Kd[rr * STRH + cc], &g_qkv[base + cfg::D]);
            cpasync16(&Vd[rr * STRH + cc], &g_qkv[base + 2 * cfg::D]);
        }
    };
    load_kv(0, 0); cp_commit();

    // load Q (scale by 0.125 — exact in fp16)
    const __half2 sc2 = __floats2half2_rn(0.125f, 0.125f);
#pragma unroll
    for (int i = 0; i < 2; i++) {
        int id = tid + i * 256;
        int rr = id >> 3, cc = (id & 7) * 8;
        const __half2* src = reinterpret_cast<const __half2*>(
            &g_qkv[(tokbase + qb * 64 + rr) * cfg::QN + h * cfg::DH + cc]);
        __half2* dst = reinterpret_cast<__half2*>(&Qs[rr * STRH + cc]);
#pragma unroll
        for (int u = 0; u < 4; u++) dst[u] = __hmul2(src[u], sc2);
    }
    __syncthreads();

    wmma::fragment<wmma::matrix_a, 16, 16, 16, __half, wmma::row_major> qf[4];
#pragma unroll
    for (int k16 = 0; k16 < 4; k16++)
        wmma::load_matrix_sync(qf[k16], Qs + (wy * 16) * STRH + k16 * 16, STRH);

    float m_r = -1e30f, l_r = 0.f;
    float O[16];
#pragma unroll
    for (int c = 0; c < 16; c++) O[c] = 0.f;

    for (int ck = 0; ck < cfg::S / 64; ck++) {
        asm volatile("cp.async.wait_group 0;\n");
        __syncthreads();   // KV ready; also protects Sf reuse from prev accumulate
        if (ck + 1 < cfg::S / 64) { load_kv((ck + 1) & 1, ck + 1); cp_commit(); }
        const __half* Ks = reinterpret_cast<const __half*>(smc + KH_OFF + (ck & 1) * TILEB);
        const __half* Vs = reinterpret_cast<const __half*>(smc + VH_OFF + (ck & 1) * TILEB);

        // scores: S = Q @ K^T
        {
            wmma::fragment<wmma::accumulator, 16, 16, 16, float> sf[2];
            wmma::fill_fragment(sf[0], 0.f);
            wmma::fill_fragment(sf[1], 0.f);
#pragma unroll
            for (int k16 = 0; k16 < 4; k16++) {
#pragma unroll
                for (int j = 0; j < 2; j++) {
                    wmma::fragment<wmma::matrix_b, 16, 16, 16, __half, wmma::col_major> bf;
                    wmma::load_matrix_sync(bf, Ks + (wx * 32 + j * 16) * STRH + k16 * 16, STRH);
                    wmma::mma_sync(sf[j], qf[k16], bf, sf[j]);
                }
            }
#pragma unroll
            for (int j = 0; j < 2; j++)
                wmma::store_matrix_sync(Sf + (wy * 16) * STRF + wx * 32 + j * 16, sf[j],
                                        STRF, wmma::mem_row_major);
        }
        __syncthreads();

        // scalar online softmax: 4 threads per row, 16 cols each; O scaled in regs
        {
            float s[16];
            float rmax = -1e30f;
#pragma unroll
            for (int c = 0; c < 16; c++) {
                s[c] = Sf[r * STRF + q4 * 16 + c];
                rmax = fmaxf(rmax, s[c]);
            }
            rmax = fmaxf(rmax, __shfl_xor_sync(0xffffffffu, rmax, 1));
            rmax = fmaxf(rmax, __shfl_xor_sync(0xffffffffu, rmax, 2));
            float mnew = fmaxf(m_r, rmax);
            float scale = __expf(m_r - mnew);
            float rs = 0.f;
#pragma unroll
            for (int c = 0; c < 16; c++) {
                float p = __expf(s[c] - mnew);
                Ph[r * STRH + q4 * 16 + c] = __float2half_rn(p);
                rs += p;
            }
            rs += __shfl_xor_sync(0xffffffffu, rs, 1);
            rs += __shfl_xor_sync(0xffffffffu, rs, 2);
            l_r = l_r * scale + rs;
            m_r = mnew;
#pragma unroll
            for (int c = 0; c < 16; c++) O[c] *= scale;
        }
        __syncthreads();   // Ph complete; all warps done reading Sf

        // O_chunk = P @ V  (result into Sf, reused)
        {
            wmma::fragment<wmma::accumulator, 16, 16, 16, float> of[2];
            wmma::fill_fragment(of[0], 0.f);
            wmma::fill_fragment(of[1], 0.f);
#pragma unroll
            for (int k16 = 0; k16 < 4; k16++) {
                wmma::fragment<wmma::matrix_a, 16, 16, 16, __half, wmma::row_major> pf;
                wmma::load_matrix_sync(pf, Ph + (wy * 16) * STRH + k16 * 16, STRH);
#pragma unroll
                for (int j = 0; j < 2; j++) {
                    wmma::fragment<wmma::matrix_b, 16, 16, 16, __half, wmma::row_major> vf;
                    wmma::load_matrix_sync(vf, Vs + (k16 * 16) * STRH + wx * 32 + j * 16, STRH);
                    wmma::mma_sync(of[j], pf, vf, of[j]);
                }
            }
#pragma unroll
            for (int j = 0; j < 2; j++)
                wmma::store_matrix_sync(Sf + (wy * 16) * STRF + wx * 32 + j * 16, of[j],
                                        STRF, wmma::mem_row_major);
        }
        __syncthreads();

        // accumulate chunk into register O (next top-of-loop sync protects Sf)
#pragma unroll
        for (int c = 0; c < 16; c++)
            O[c] += Sf[r * STRF + q4 * 16 + c];
    }

    // normalize + write half output
    {
        float inv = 1.f / l_r;
        __half* orow = &g_o[(tokbase + qb * 64 + r) * cfg::D + h * cfg::DH + q4 * 16];
#pragma unroll
        for (int cc = 0; cc < 4; cc++) {
            __half2 h0 = __floats2half2_rn(O[cc * 4 + 0] * inv, O[cc * 4 + 1] * inv);
            __half2 h1 = __floats2half2_rn(O[cc * 4 + 2] * inv, O[cc * 4 + 3] * inv);
            uint2 u;
            u.x = reinterpret_cast<uint32_t&>(h0);
            u.y = reinterpret_cast<uint32_t&>(h1);
            *reinterpret_cast<uint2*>(&orow[cc * 4]) = u;
        }
    }
}

// -------------------- host launcher --------------------
extern "C" void kernel_launch(void* const* d_in, const int* in_sizes, int n_in,
                              void* d_out, int out_size) {
    using namespace cfg;
    const void*  idx      = d_in[0];
    const float* tok_emb  = (const float*)d_in[1];
    const float* seg_emb  = (const float*)d_in[2];
    const float* pos_emb  = (const float*)d_in[3];
    const float* ln_emb_g = (const float*)d_in[4];
    const float* ln_emb_b = (const float*)d_in[5];
    const float* Wq       = (const float*)d_in[6];
    const float* Wk       = (const float*)d_in[7];
    const float* Wv       = (const float*)d_in[8];
    const float* Wo       = (const float*)d_in[9];
    const float* bo       = (const float*)d_in[10];
    const float* ln1_g    = (const float*)d_in[11];
    const float* ln1_b    = (const float*)d_in[12];
    const float* ln2_g    = (const float*)d_in[13];
    const float* ln2_b    = (const float*)d_in[14];
    const float* W1       = (const float*)d_in[15];
    const float* b1       = (const float*)d_in[16];
    const float* W2       = (const float*)d_in[17];
    const float* b2       = (const float*)d_in[18];
    const float* lnf_g    = (const float*)d_in[19];
    const float* lnf_b    = (const float*)d_in[20];
    float* out = (float*)d_out;

    float *px;
    __half *ph, *pq, *po, *pf, *pwq, *pwo, *pw1, *pw2;
    cudaGetSymbolAddress((void**)&px, g_x);
    cudaGetSymbolAddress((void**)&ph, g_h);
    cudaGetSymbolAddress((void**)&pq, g_qkv);
    cudaGetSymbolAddress((void**)&po, g_o);
    cudaGetSymbolAddress((void**)&pf, g_ff);
    cudaGetSymbolAddress((void**)&pwq, g_wqkv);
    cudaGetSymbolAddress((void**)&pwo, g_wo);
    cudaGetSymbolAddress((void**)&pw1, g_w1);
    cudaGetSymbolAddress((void**)&pw2, g_w2);

    cudaFuncSetAttribute((const void*)gemm_fp16<0, __half>, cudaFuncAttributeMaxDynamicSharedMemorySize, gk::SMEM_BYTES);
    cudaFuncSetAttribute((const void*)gemm_fp16<1, float>,  cudaFuncAttributeMaxDynamicSharedMemorySize, gk::SMEM_BYTES);
    cudaFuncSetAttribute((const void*)gemm_fp16<2, __half>, cudaFuncAttributeMaxDynamicSharedMemorySize, gk::SMEM_BYTES);
    cudaFuncSetAttribute((const void*)attn_kernel, cudaFuncAttributeMaxDynamicSharedMemorySize, ak::SMEM_BYTES);

    // launches 1-3: prep; launch #4 = QKV GEMM (ncu capture slot)
    detect_idx_kernel<<<1, 256>>>(idx);
    {
        size_t total = (size_t)L * D * QN;
        repack_kernel<<<(int)((total + 255) / 256), 256>>>(Wq, Wk, Wv);
    }
    embed_ln_ln1_kernel<<<T, 256>>>(idx, tok_emb, seg_emb, pos_emb,
                                    ln_emb_g, ln_emb_b, ln1_g, ln1_b);

    bool prepped = false;
    for (int l = 0; l < L; l++) {
        if (l > 0)
            ln_half_kernel<<<T, 256>>>(px, ph, ln1_g + (size_t)l * D, ln1_b + (size_t)l * D);
        gemm_fp16<0, __half><<<dim3(QN / 128, T / 128), 128, gk::SMEM_BYTES>>>(
            ph, pwq + (size_t)l * D * QN, pq, nullptr, nullptr, T, QN, D);
        attn_kernel<<<dim3(S / 64, H, B), 256, ak::SMEM_BYTES>>>();
        if (!prepped) {
            size_t n4 = ((size_t)L * D * D + 2 * (size_t)L * D * FF) / 4;
            prep_weights_kernel<<<(int)((n4 + 255) / 256), 256>>>(Wo, W1, W2);
            prepped = true;
        }
        gemm_fp16<1, float><<<dim3(D / 128, T / 128), 128, gk::SMEM_BYTES>>>(
            po, pwo + (size_t)l * D * D, px, bo + (size_t)l * D, px, T, D, D);
        ln_half_kernel<<<T, 256>>>(px, ph, ln2_g + (size_t)l * D, ln2_b + (size_t)l * D);
        gemm_fp16<2, __half><<<dim3(FF / 128, T / 128), 128, gk::SMEM_BYTES>>>(
            ph, pw1 + (size_t)l * D * FF, pf, b1 + (size_t)l * FF, nullptr, T, FF, D);
        gemm_fp16<1, float><<<dim3(D / 128, T / 128), 128, gk::SMEM_BYTES>>>(
            pf, pw2 + (size_t)l * FF * D, px, b2 + (size_t)l * D, px, T, D, FF);
    }

    ln_float_kernel<<<T, 256>>>(px, out, lnf_g, lnf_b);
}

// round 15
// speedup vs baseline: 1.0105x; 1.0105x over previous
#include <cuda_runtime.h>
#include <mma.h>
#include <cuda_fp16.h>
#include <cstdint>
#include <cstddef>

using namespace nvcuda;

namespace cfg {
constexpr int B = 16, S = 512, D = 768, H = 12, DH = 64, L = 12, FF = 3072, V = 30522;
constexpr int T = B * S;          // 8192 tokens
constexpr int QN = 3 * D;         // 2304 (q|k|v packed)
}

// -------------------- scratch (static device memory; no allocs) --------------------
__device__ float  g_x[(size_t)cfg::T * cfg::D];              // residual (fp32)
__device__ __half g_h[(size_t)cfg::T * cfg::D];              // LN out (half)
__device__ __half g_qkv[(size_t)cfg::T * cfg::QN];           // q|k|v (half)
__device__ __half g_o[(size_t)cfg::T * cfg::D];              // attn out (half)
__device__ __half g_ff[(size_t)cfg::T * cfg::FF];            // FFN hidden (half)
__device__ __half g_wqkv[(size_t)cfg::L * cfg::D * cfg::QN]; // packed qkv W (half)
__device__ __half g_wo[(size_t)cfg::L * cfg::D * cfg::D];
__device__ __half g_w1[(size_t)cfg::L * cfg::D * cfg::FF];
__device__ __half g_w2[(size_t)cfg::L * cfg::FF * cfg::D];
__device__ int g_idx64;

// -------------------- idx dtype probe --------------------
__global__ void detect_idx_kernel(const void* p) {
    const long long* q = (const long long*)p;
    __shared__ int sbad;
    if (threadIdx.x == 0) sbad = 0;
    __syncthreads();
    int bad = 0;
    for (int i = threadIdx.x; i < 4096; i += 256) {
        long long v = q[i];
        if (v < 0 || v >= (long long)cfg::V) bad = 1;
    }
    if (bad) atomicOr(&sbad, 1);
    __syncthreads();
    if (threadIdx.x == 0) g_idx64 = sbad ? 0 : 1;
}

// -------------------- weight repack: (L,H,D,DH)x3 -> (L, D, 2304) half -------------
__global__ void repack_kernel(const float* __restrict__ Wq,
                              const float* __restrict__ Wk,
                              const float* __restrict__ Wv) {
    size_t i = (size_t)blockIdx.x * blockDim.x + threadIdx.x;
    size_t total = (size_t)cfg::L * cfg::D * cfg::QN;
    if (i >= total) return;
    int j = (int)(i % cfg::QN);
    size_t ld = i / cfg::QN;
    int d = (int)(ld % cfg::D);
    int l = (int)(ld / cfg::D);
    const float* W;
    int jj = j;
    if (j < cfg::D) { W = Wq; }
    else if (j < 2 * cfg::D) { W = Wk; jj = j - cfg::D; }
    else { W = Wv; jj = j - 2 * cfg::D; }
    int h = jj / cfg::DH, k = jj % cfg::DH;
    g_wqkv[i] = __float2half_rn(W[((((size_t)l * cfg::H + h) * cfg::D) + d) * cfg::DH + k]);
}

// -------------------- merged half convert of Wo, W1, W2 --------------------
__global__ void prep_weights_kernel(const float* __restrict__ Wo,
                                    const float* __restrict__ W1,
                                    const float* __restrict__ W2) {
    using namespace cfg;
    constexpr size_t N1 = (size_t)L * D * D / 4;
    constexpr size_t N2 = N1 + (size_t)L * D * FF / 4;
    constexpr size_t N3 = N2 + (size_t)L * FF * D / 4;
    size_t i = (size_t)blockIdx.x * blockDim.x + threadIdx.x;
    if (i >= N3) return;
    const float4* src;
    __half* dst;
    size_t off;
    if (i < N1)      { src = (const float4*)Wo; dst = g_wo; off = i; }
    else if (i < N2) { src = (const float4*)W1; dst = g_w1; off = i - N1; }
    else             { src = (const float4*)W2; dst = g_w2; off = i - N2; }
    float4 v = src[off];
    __half2 h0 = __floats2half2_rn(v.x, v.y);
    __half2 h1 = __floats2half2_rn(v.z, v.w);
    uint2 u;
    u.x = reinterpret_cast<uint32_t&>(h0);
    u.y = reinterpret_cast<uint32_t&>(h1);
    *reinterpret_cast<uint2*>(dst + off * 4) = u;
}

// -------------------- block reduction helper (256 threads) --------------------
__device__ __forceinline__ float block_sum256(float v, float* red) {
    int lane = threadIdx.x & 31, warp = threadIdx.x >> 5;
#pragma unroll
    for (int o = 16; o; o >>= 1) v += __shfl_xor_sync(0xffffffffu, v, o);
    if (lane == 0) red[warp] = v;
    __syncthreads();
    if (threadIdx.x == 0) {
        float s = 0.f;
#pragma unroll
        for (int i = 0; i < 8; i++) s += red[i];
        red[8] = s;
    }
    __syncthreads();
    float r = red[8];
    __syncthreads();
    return r;
}

// -------------------- fused embedding + LN_emb + LN1(layer0) --------------------
__global__ void embed_ln_ln1_kernel(const void* __restrict__ idxp,
                                    const float* __restrict__ tok,
                                    const float* __restrict__ seg,
                                    const float* __restrict__ pos,
                                    const float* __restrict__ ge, const float* __restrict__ be,
                                    const float* __restrict__ g1, const float* __restrict__ b1) {
    __shared__ float red[9];
    int t = blockIdx.x;
    int s = t % cfg::S;
    long long id;
    if (g_idx64) id = ((const long long*)idxp)[t];
    else         id = (long long)((const int*)idxp)[t];
    int sg = (s >= cfg::S / 2 + 1) ? 1 : 0;
    float v[3];
#pragma unroll
    for (int i = 0; i < 3; i++) {
        int c = threadIdx.x + i * 256;
        v[i] = tok[(size_t)id * cfg::D + c] + seg[(size_t)sg * cfg::D + c] + pos[(size_t)s * cfg::D + c];
    }
    float mean = block_sum256(v[0] + v[1] + v[2], red) * (1.f / cfg::D);
    float q = 0.f;
#pragma unroll
    for (int i = 0; i < 3; i++) { float d = v[i] - mean; q += d * d; }
    float var = block_sum256(q, red) * (1.f / cfg::D);
    float inv = rsqrtf(var + 1e-5f);
    float x[3];
#pragma unroll
    for (int i = 0; i < 3; i++) {
        int c = threadIdx.x + i * 256;
        x[i] = (v[i] - mean) * inv * ge[c] + be[c];
        g_x[(size_t)t * cfg::D + c] = x[i];
    }
    float mean2 = block_sum256(x[0] + x[1] + x[2], red) * (1.f / cfg::D);
    float q2 = 0.f;
#pragma unroll
    for (int i = 0; i < 3; i++) { float d = x[i] - mean2; q2 += d * d; }
    float var2 = block_sum256(q2, red) * (1.f / cfg::D);
    float inv2 = rsqrtf(var2 + 1e-5f);
#pragma unroll
    for (int i = 0; i < 3; i++) {
        int c = threadIdx.x + i * 256;
        g_h[(size_t)t * cfg::D + c] = __float2half_rn((x[i] - mean2) * inv2 * g1[c] + b1[c]);
    }
}

// -------------------- LayerNorm to half (GEMM operand) --------------------
__global__ void ln_half_kernel(const float* __restrict__ src, __half* __restrict__ dst,
                               const float* __restrict__ g, const float* __restrict__ b) {
    __shared__ float red[9];
    int t = blockIdx.x;
    const float* x = src + (size_t)t * cfg::D;
    float v[3];
#pragma unroll
    for (int i = 0; i < 3; i++) v[i] = x[threadIdx.x + i * 256];
    float mean = block_sum256(v[0] + v[1] + v[2], red) * (1.f / cfg::D);
    float q = 0.f;
#pragma unroll
    for (int i = 0; i < 3; i++) { float d = v[i] - mean; q += d * d; }
    float var = block_sum256(q, red) * (1.f / cfg::D);
    float inv = rsqrtf(var + 1e-5f);
#pragma unroll
    for (int i = 0; i < 3; i++) {
        int c = threadIdx.x + i * 256;
        dst[(size_t)t * cfg::D + c] = __float2half_rn((v[i] - mean) * inv * g[c] + b[c]);
    }
}

// -------------------- final LayerNorm to fp32 --------------------
__global__ void ln_float_kernel(const float* __restrict__ src, float* __restrict__ dst,
                                const float* __restrict__ g, const float* __restrict__ b) {
    __shared__ float red[9];
    int t = blockIdx.x;
    const float* x = src + (size_t)t * cfg::D;
    float v[3];
#pragma unroll
    for (int i = 0; i < 3; i++) v[i] = x[threadIdx.x + i * 256];
    float mean = block_sum256(v[0] + v[1] + v[2], red) * (1.f / cfg::D);
    float q = 0.f;
#pragma unroll
    for (int i = 0; i < 3; i++) { float d = v[i] - mean; q += d * d; }
    float var = block_sum256(q, red) * (1.f / cfg::D);
    float inv = rsqrtf(var + 1e-5f);
#pragma unroll
    for (int i = 0; i < 3; i++) {
        int c = threadIdx.x + i * 256;
        dst[(size_t)t * cfg::D + c] = (v[i] - mean) * inv * g[c] + b[c];
    }
}

// -------------------- cp.async helpers --------------------
__device__ __forceinline__ void cpasync16(void* smem, const void* gmem) {
    uint32_t s = (uint32_t)__cvta_generic_to_shared(smem);
    asm volatile("cp.async.cg.shared.global [%0], [%1], 16;\n" :: "r"(s), "l"(gmem));
}
__device__ __forceinline__ void cp_commit() {
    asm volatile("cp.async.commit_group;\n");
}

// -------------------- pipelined fp16 WMMA GEMM, warp tile 64x64, BK=64 -------------
// (R13 configuration — best measured; mainloop frozen)
// C[M,N] = A[M,K] @ B[K,N]; A,B half row-major; accum fp32.
// 128 threads (2x2 warps), block 128x128, BK=64, 2-stage cp.async pipeline.
// EPI: 0 = store half, 1 = float C = res + AB + bias, 2 = half C = relu(AB + bias)
namespace gk {
constexpr int BM = 128, BN = 128, BK = 64;
constexpr int ASTR = 72;                   // halfs (64 + 8 pad)
constexpr int BSTR = 136;                  // halfs (128 + 8 pad)
constexpr int A_TILE = BM * ASTR;          // 9216 halfs
constexpr int B_TILE = BK * BSTR;          // 8704 halfs
constexpr int STAGE_H = A_TILE + B_TILE;   // 17920 halfs (35840 B)
constexpr int ESTR = 132;                  // fp32 epilogue stride
constexpr int SMEM_BYTES = 2 * STAGE_H * 2; // 71680 (covers epilogue 67584)
}

template <int EPI, typename OutT>
__global__ __launch_bounds__(128, 2)
void gemm_fp16(const __half* __restrict__ A, const __half* __restrict__ B,
               OutT* __restrict__ C, const float* __restrict__ bias,
               const float* __restrict__ res, int M, int N, int K) {
    using namespace gk;
    extern __shared__ char smc[];
    __half* sm = reinterpret_cast<__half*>(smc);

    const int tid = threadIdx.x, warp = tid >> 5;
    const int wy = warp >> 1, wx = warp & 1;     // 2x2 warps, warp tile 64x64
    const int bm = blockIdx.y * BM, bn = blockIdx.x * BN;

    wmma::fragment<wmma::accumulator, 16, 16, 16, float> acc[4][4];
#pragma unroll
    for (int i = 0; i < 4; i++)
#pragma unroll
        for (int j = 0; j < 4; j++) wmma::fill_fragment(acc[i][j], 0.f);

    auto load_tiles = [&](int st, int kt) {
        __half* dstA = sm + st * STAGE_H;
        const __half* srcA = A + (size_t)bm * K + kt * BK;
#pragma unroll
        for (int i = 0; i < 8; i++) {                 // 128 rows x 8 chunks of 8 halfs
            int id = tid + i * 128;
            int r = id >> 3, c = (id & 7) * 8;
            cpasync16(&dstA[r * ASTR + c], &srcA[(size_t)r * K + c]);
        }
        __half* dstB = sm + st * STAGE_H + A_TILE;
        const __half* srcB = B + (size_t)(kt * BK) * N + bn;
#pragma unroll
        for (int i = 0; i < 8; i++) {                 // 64 rows x 16 chunks
            int id = tid + i * 128;
            int r = id >> 4, c = (id & 15) * 8;
            cpasync16(&dstB[r * BSTR + c], &srcB[(size_t)r * N + c]);
        }
    };

    const int nk = K / BK;
    load_tiles(0, 0); cp_commit();

    for (int kt = 0; kt < nk; kt++) {
        asm volatile("cp.async.wait_group 0;\n");
        __syncthreads();
        if (kt + 1 < nk) { load_tiles((kt + 1) & 1, kt + 1); cp_commit(); }

        const __half* a = sm + (kt & 1) * STAGE_H;
        const __half* b = a + A_TILE;
#pragma unroll
        for (int kk = 0; kk < BK; kk += 16) {
            wmma::fragment<wmma::matrix_a, 16, 16, 16, __half, wmma::row_major> af[4];
            wmma::fragment<wmma::matrix_b, 16, 16, 16, __half, wmma::row_major> bf[4];
#pragma unroll
            for (int i = 0; i < 4; i++)
                wmma::load_matrix_sync(af[i], a + (wy * 64 + i * 16) * ASTR + kk, ASTR);
#pragma unroll
            for (int j = 0; j < 4; j++)
                wmma::load_matrix_sync(bf[j], b + kk * BSTR + wx * 64 + j * 16, BSTR);
#pragma unroll
            for (int i = 0; i < 4; i++)
#pragma unroll
                for (int j = 0; j < 4; j++)
                    wmma::mma_sync(acc[i][j], af[i], bf[j], acc[i][j]);
        }
        __syncthreads();
    }

    // epilogue: stage fp32 128x128 in smem, fused write
    float* epi = reinterpret_cast<float*>(smc);
#pragma unroll
    for (int i = 0; i < 4; i++)
#pragma unroll
        for (int j = 0; j < 4; j++)
            wmma::store_matrix_sync(epi + (wy * 64 + i * 16) * ESTR + wx * 64 + j * 16,
                                    acc[i][j], ESTR, wmma::mem_row_major);
    __syncthreads();
#pragma unroll
    for (int it = 0; it < 32; it++) {
        int id = tid + it * 128;
        int r = id >> 5, c4 = (id & 31) * 4;
        float4 v = *reinterpret_cast<float4*>(&epi[r * ESTR + c4]);
        int gc = bn + c4;
        size_t gi = (size_t)(bm + r) * N + gc;
        if (EPI == 1) {
            float4 rv = *reinterpret_cast<const float4*>(&res[gi]);
            float4 bv = *reinterpret_cast<const float4*>(&bias[gc]);
            v.x += rv.x + bv.x; v.y += rv.y + bv.y; v.z += rv.z + bv.z; v.w += rv.w + bv.w;
            *reinterpret_cast<float4*>(&((float*)C)[gi]) = v;
        } else {
            if (EPI == 2) {
                float4 bv = *reinterpret_cast<const float4*>(&bias[gc]);
                v.x = fmaxf(v.x + bv.x, 0.f); v.y = fmaxf(v.y + bv.y, 0.f);
                v.z = fmaxf(v.z + bv.z, 0.f); v.w = fmaxf(v.w + bv.w, 0.f);
            }
            __half2 h0 = __floats2half2_rn(v.x, v.y);
            __half2 h1 = __floats2half2_rn(v.z, v.w);
            uint2 u;
            u.x = reinterpret_cast<uint32_t&>(h0);
            u.y = reinterpret_cast<uint32_t&>(h1);
            *reinterpret_cast<uint2*>(&((__half*)C)[gi]) = u;
        }
    }
}

// -------------------- BM=64 variant for narrow-N GEMMs (Wo, W2) --------------------
// Grid doubles (M/64 rows) to fix wave quantization at N=768; 3 blocks/SM.
// 128 threads (2x2 warps), warp tile 32x64, BK=64, 2-stage. EPI=1 only (fp32 out).
namespace gk64 {
constexpr int BM = 64, BN = 128, BK = 64;
constexpr int ASTR = 72;
constexpr int BSTR = 136;
constexpr int A_TILE = BM * ASTR;          // 4608 halfs
constexpr int B_TILE = BK * BSTR;          // 8704 halfs
constexpr int STAGE_H = A_TILE + B_TILE;   // 13312 halfs (26624 B)
constexpr int ESTR = 132;
constexpr int SMEM_BYTES = 2 * STAGE_H * 2; // 53248 (covers epilogue 64*132*4=33792)
}

__global__ __launch_bounds__(128, 3)
void gemm_fp16_bm64(const __half* __restrict__ A, const __half* __restrict__ B,
                    float* __restrict__ C, const float* __restrict__ bias,
                    const float* __restrict__ res, int M, int N, int K) {
    using namespace gk64;
    extern __shared__ char smc[];
    __half* sm = reinterpret_cast<__half*>(smc);

    const int tid = threadIdx.x, warp = tid >> 5;
    const int wy = warp >> 1, wx = warp & 1;     // 2x2 warps, warp tile 32x64
    const int bm = blockIdx.y * BM, bn = blockIdx.x * BN;

    wmma::fragment<wmma::accumulator, 16, 16, 16, float> acc[2][4];
#pragma unroll
    for (int i = 0; i < 2; i++)
#pragma unroll
        for (int j = 0; j < 4; j++) wmma::fill_fragment(acc[i][j], 0.f);

    auto load_tiles = [&](int st, int kt) {
        __half* dstA = sm + st * STAGE_H;
        const __half* srcA = A + (size_t)bm * K + kt * BK;
#pragma unroll
        for (int i = 0; i < 4; i++) {                 // 64 rows x 8 chunks of 8 halfs
            int id = tid + i * 128;
            int r = id >> 3, c = (id & 7) * 8;
            cpasync16(&dstA[r * ASTR + c], &srcA[(size_t)r * K + c]);
        }
        __half* dstB = sm + st * STAGE_H + A_TILE;
        const __half* srcB = B + (size_t)(kt * BK) * N + bn;
#pragma unroll
        for (int i = 0; i < 8; i++) {                 // 64 rows x 16 chunks
            int id = tid + i * 128;
            int r = id >> 4, c = (id & 15) * 8;
            cpasync16(&dstB[r * BSTR + c], &srcB[(size_t)r * N + c]);
        }
    };

    const int nk = K / BK;
    load_tiles(0, 0); cp_commit();

    for (int kt = 0; kt < nk; kt++) {
        asm volatile("cp.async.wait_group 0;\n");
        __syncthreads();
        if (kt + 1 < nk) { load_tiles((kt + 1) & 1, kt + 1); cp_commit(); }

        const __half* a = sm + (kt & 1) * STAGE_H;
        const __half* b = a + A_TILE;
#pragma unroll
        for (int kk = 0; kk < BK; kk += 16) {
            wmma::fragment<wmma::matrix_a, 16, 16, 16, __half, wmma::row_major> af[2];
            wmma::fragment<wmma::matrix_b, 16, 16, 16, __half, wmma::row_major> bf[4];
#pragma unroll
            for (int i = 0; i < 2; i++)
                wmma::load_matrix_sync(af[i], a + (wy * 32 + i * 16) * ASTR + kk, ASTR);
#pragma unroll
            for (int j = 0; j < 4; j++)
                wmma::load_matrix_sync(bf[j], b + kk * BSTR + wx * 64 + j * 16, BSTR);
#pragma unroll
            for (int i = 0; i < 2; i++)
#pragma unroll
                for (int j = 0; j < 4; j++)
                    wmma::mma_sync(acc[i][j], af[i], bf[j], acc[i][j]);
        }
        __syncthreads();
    }

    // epilogue: stage fp32 64x128 in smem, fused residual+bias write
    float* epi = reinterpret_cast<float*>(smc);
#pragma unroll
    for (int i = 0; i < 2; i++)
#pragma unroll
        for (int j = 0; j < 4; j++)
            wmma::store_matrix_sync(epi + (wy * 32 + i * 16) * ESTR + wx * 64 + j * 16,
                                    acc[i][j], ESTR, wmma::mem_row_major);
    __syncthreads();
#pragma unroll
    for (int it = 0; it < 16; it++) {
        int id = tid + it * 128;
        int r = id >> 5, c4 = (id & 31) * 4;
        float4 v = *reinterpret_cast<float4*>(&epi[r * ESTR + c4]);
        int gc = bn + c4;
        size_t gi = (size_t)(bm + r) * N + gc;
        float4 rv = *reinterpret_cast<const float4*>(&res[gi]);
        float4 bv = *reinterpret_cast<const float4*>(&bias[gc]);
        v.x += rv.x + bv.x; v.y += rv.y + bv.y; v.z += rv.z + bv.z; v.w += rv.w + bv.w;
        *reinterpret_cast<float4*>(&C[gi]) = v;
    }
}

// -------------------- fp16 WMMA flash attention, register O accumulator ------------
// grid (S/64, H, B), 256 threads (8 warps as 4x2; warp tile 16x32).
namespace ak {
constexpr int STRH = 72;                       // half tile stride
constexpr int STRF = 68;                       // fp32 stride
constexpr int TILEB = 64 * STRH * 2;           // 9216 B per half tile
constexpr int QH_OFF = 0;
constexpr int KH_OFF = QH_OFF + TILEB;         // K0, K1
constexpr int VH_OFF = KH_OFF + 2 * TILEB;     // V0, V1
constexpr int PH_OFF = VH_OFF + 2 * TILEB;     // half P tile
constexpr int SF_OFF = PH_OFF + TILEB;         // fp32 scores / PV result (reused)
constexpr int SMEM_BYTES = SF_OFF + 64 * STRF * 4;  // 72704
}

__global__ __launch_bounds__(256)
void attn_kernel() {
    using namespace ak;
    extern __shared__ char smc[];
    __half* Qs = reinterpret_cast<__half*>(smc + QH_OFF);
    __half* Ph = reinterpret_cast<__half*>(smc + PH_OFF);
    float*  Sf = reinterpret_cast<float*>(smc + SF_OFF);

    const int qb = blockIdx.x, h = blockIdx.y, b = blockIdx.z;
    const int tid = threadIdx.x, warp = tid >> 5;
    const int wy = warp >> 1, wx = warp & 1;
    const int r = tid >> 2, q4 = tid & 3;
    const size_t tokbase = (size_t)b * cfg::S;

    auto load_kv = [&](int st, int ck) {
        __half* Kd = reinterpret_cast<__half*>(smc + KH_OFF + st * TILEB);
        __half* Vd = reinterpret_cast<__half*>(smc + VH_OFF + st * TILEB);
#pragma unroll
        for (int i = 0; i < 2; i++) {
            int id = tid + i * 256;                  // 512 chunks of 8 halfs
            int rr = id >> 3, cc = (id & 7) * 8;
            size_t base = (tokbase + ck * 64 + rr) * cfg::QN + h * cfg::DH + cc;
            cpasync16(&Kd[rr * STRH + cc], &g_qkv[base + cfg::D]);
            cpasync16(&Vd[rr * STRH + cc], &g_qkv[base + 2 * cfg::D]);
        }
    };
    load_kv(0, 0); cp_commit();

    // load Q (scale by 0.125 — exact in fp16)
    const __half2 sc2 = __floats2half2_rn(0.125f, 0.125f);
#pragma unroll
    for (int i = 0; i < 2; i++) {
        int id = tid + i * 256;
        int rr = id >> 3, cc = (id & 7) * 8;
        const __half2* src = reinterpret_cast<const __half2*>(
            &g_qkv[(tokbase + qb * 64 + rr) * cfg::QN + h * cfg::DH + cc]);
        __half2* dst = reinterpret_cast<__half2*>(&Qs[rr * STRH + cc]);
#pragma unroll
        for (int u = 0; u < 4; u++) dst[u] = __hmul2(src[u], sc2);
    }
    __syncthreads();

    wmma::fragment<wmma::matrix_a, 16, 16, 16, __half, wmma::row_major> qf[4];
#pragma unroll
    for (int k16 = 0; k16 < 4; k16++)
        wmma::load_matrix_sync(qf[k16], Qs + (wy * 16) * STRH + k16 * 16, STRH);

    float m_r = -1e30f, l_r = 0.f;
    float O[16];
#pragma unroll
    for (int c = 0; c < 16; c++) O[c] = 0.f;

    for (int ck = 0; ck < cfg::S / 64; ck++) {
        asm volatile("cp.async.wait_group 0;\n");
        __syncthreads();   // KV ready; also protects Sf reuse from prev accumulate
        if (ck + 1 < cfg::S / 64) { load_kv((ck + 1) & 1, ck + 1); cp_commit(); }
        const __half* Ks = reinterpret_cast<const __half*>(smc + KH_OFF + (ck & 1) * TILEB);
        const __half* Vs = reinterpret_cast<const __half*>(smc + VH_OFF + (ck & 1) * TILEB);

        // scores: S = Q @ K^T
        {
            wmma::fragment<wmma::accumulator, 16, 16, 16, float> sf[2];
            wmma::fill_fragment(sf[0], 0.f);
            wmma::fill_fragment(sf[1], 0.f);
#pragma unroll
            for (int k16 = 0; k16 < 4; k16++) {
#pragma unroll
                for (int j = 0; j < 2; j++) {
                    wmma::fragment<wmma::matrix_b, 16, 16, 16, __half, wmma::col_major> bf;
                    wmma::load_matrix_sync(bf, Ks + (wx * 32 + j * 16) * STRH + k16 * 16, STRH);
                    wmma::mma_sync(sf[j], qf[k16], bf, sf[j]);
                }
            }
#pragma unroll
            for (int j = 0; j < 2; j++)
                wmma::store_matrix_sync(Sf + (wy * 16) * STRF + wx * 32 + j * 16, sf[j],
                                        STRF, wmma::mem_row_major);
        }
        __syncthreads();

        // scalar online softmax: 4 threads per row, 16 cols each; O scaled in regs
        {
            float s[16];
            float rmax = -1e30f;
#pragma unroll
            for (int c = 0; c < 16; c++) {
                s[c] = Sf[r * STRF + q4 * 16 + c];
                rmax = fmaxf(rmax, s[c]);
            }
            rmax = fmaxf(rmax, __shfl_xor_sync(0xffffffffu, rmax, 1));
            rmax = fmaxf(rmax, __shfl_xor_sync(0xffffffffu, rmax, 2));
            float mnew = fmaxf(m_r, rmax);
            float scale = __expf(m_r - mnew);
            float rs = 0.f;
#pragma unroll
            for (int c = 0; c < 16; c++) {
                float p = __expf(s[c] - mnew);
                Ph[r * STRH + q4 * 16 + c] = __float2half_rn(p);
                rs += p;
            }
            rs += __shfl_xor_sync(0xffffffffu, rs, 1);
            rs += __shfl_xor_sync(0xffffffffu, rs, 2);
            l_r = l_r * scale + rs;
            m_r = mnew;
#pragma unroll
            for (int c = 0; c < 16; c++) O[c] *= scale;
        }
        __syncthreads();   // Ph complete; all warps done reading Sf

        // O_chunk = P @ V  (result into Sf, reused)
        {
            wmma::fragment<wmma::accumulator, 16, 16, 16, float> of[2];
            wmma::fill_fragment(of[0], 0.f);
            wmma::fill_fragment(of[1], 0.f);
#pragma unroll
            for (int k16 = 0; k16 < 4; k16++) {
                wmma::fragment<wmma::matrix_a, 16, 16, 16, __half, wmma::row_major> pf;
                wmma::load_matrix_sync(pf, Ph + (wy * 16) * STRH + k16 * 16, STRH);
#pragma unroll
                for (int j = 0; j < 2; j++) {
                    wmma::fragment<wmma::matrix_b, 16, 16, 16, __half, wmma::row_major> vf;
                    wmma::load_matrix_sync(vf, Vs + (k16 * 16) * STRH + wx * 32 + j * 16, STRH);
                    wmma::mma_sync(of[j], pf, vf, of[j]);
                }
            }
#pragma unroll
            for (int j = 0; j < 2; j++)
                wmma::store_matrix_sync(Sf + (wy * 16) * STRF + wx * 32 + j * 16, of[j],
                                        STRF, wmma::mem_row_major);
        }
        __syncthreads();

        // accumulate chunk into register O (next top-of-loop sync protects Sf)
#pragma unroll
        for (int c = 0; c < 16; c++)
            O[c] += Sf[r * STRF + q4 * 16 + c];
    }

    // normalize + write half output
    {
        float inv = 1.f / l_r;
        __half* orow = &g_o[(tokbase + qb * 64 + r) * cfg::D + h * cfg::DH + q4 * 16];
#pragma unroll
        for (int cc = 0; cc < 4; cc++) {
            __half2 h0 = __floats2half2_rn(O[cc * 4 + 0] * inv, O[cc * 4 + 1] * inv);
            __half2 h1 = __floats2half2_rn(O[cc * 4 + 2] * inv, O[cc * 4 + 3] * inv);
            uint2 u;
            u.x = reinterpret_cast<uint32_t&>(h0);
            u.y = reinterpret_cast<uint32_t&>(h1);
            *reinterpret_cast<uint2*>(&orow[cc * 4]) = u;
        }
    }
}

// -------------------- host launcher --------------------
extern "C" void kernel_launch(void* const* d_in, const int* in_sizes, int n_in,
                              void* d_out, int out_size) {
    using namespace cfg;
    const void*  idx      = d_in[0];
    const float* tok_emb  = (const float*)d_in[1];
    const float* seg_emb  = (const float*)d_in[2];
    const float* pos_emb  = (const float*)d_in[3];
    const float* ln_emb_g = (const float*)d_in[4];
    const float* ln_emb_b = (const float*)d_in[5];
    const float* Wq       = (const float*)d_in[6];
    const float* Wk       = (const float*)d_in[7];
    const float* Wv       = (const float*)d_in[8];
    const float* Wo       = (const float*)d_in[9];
    const float* bo       = (const float*)d_in[10];
    const float* ln1_g    = (const float*)d_in[11];
    const float* ln1_b    = (const float*)d_in[12];
    const float* ln2_g    = (const float*)d_in[13];
    const float* ln2_b    = (const float*)d_in[14];
    const float* W1       = (const float*)d_in[15];
    const float* b1       = (const float*)d_in[16];
    const float* W2       = (const float*)d_in[17];
    const float* b2       = (const float*)d_in[18];
    const float* lnf_g    = (const float*)d_in[19];
    const float* lnf_b    = (const float*)d_in[20];
    float* out = (float*)d_out;

    float *px;
    __half *ph, *pq, *po, *pf, *pwq, *pwo, *pw1, *pw2;
    cudaGetSymbolAddress((void**)&px, g_x);
    cudaGetSymbolAddress((void**)&ph, g_h);
    cudaGetSymbolAddress((void**)&pq, g_qkv);
    cudaGetSymbolAddress((void**)&po, g_o);
    cudaGetSymbolAddress((void**)&pf, g_ff);
    cudaGetSymbolAddress((void**)&pwq, g_wqkv);
    cudaGetSymbolAddress((void**)&pwo, g_wo);
    cudaGetSymbolAddress((void**)&pw1, g_w1);
    cudaGetSymbolAddress((void**)&pw2, g_w2);

    cudaFuncSetAttribute((const void*)gemm_fp16<0, __half>, cudaFuncAttributeMaxDynamicSharedMemorySize, gk::SMEM_BYTES);
    cudaFuncSetAttribute((const void*)gemm_fp16<2, __half>, cudaFuncAttributeMaxDynamicSharedMemorySize, gk::SMEM_BYTES);
    cudaFuncSetAttribute((const void*)gemm_fp16_bm64, cudaFuncAttributeMaxDynamicSharedMemorySize, gk64::SMEM_BYTES);
    cudaFuncSetAttribute((const void*)attn_kernel, cudaFuncAttributeMaxDynamicSharedMemorySize, ak::SMEM_BYTES);

    // launches 1-3: prep; launch #4 = QKV GEMM (ncu capture slot)
    detect_idx_kernel<<<1, 256>>>(idx);
    {
        size_t total = (size_t)L * D * QN;
        repack_kernel<<<(int)((total + 255) / 256), 256>>>(Wq, Wk, Wv);
    }
    embed_ln_ln1_kernel<<<T, 256>>>(idx, tok_emb, seg_emb, pos_emb,
                                    ln_emb_g, ln_emb_b, ln1_g, ln1_b);

    bool prepped = false;
    for (int l = 0; l < L; l++) {
        if (l > 0)
            ln_half_kernel<<<T, 256>>>(px, ph, ln1_g + (size_t)l * D, ln1_b + (size_t)l * D);
        gemm_fp16<0, __half><<<dim3(QN / 128, T / 128), 128, gk::SMEM_BYTES>>>(
            ph, pwq + (size_t)l * D * QN, pq, nullptr, nullptr, T, QN, D);
        attn_kernel<<<dim3(S / 64, H, B), 256, ak::SMEM_BYTES>>>();
        if (!prepped) {
            size_t n4 = ((size_t)L * D * D + 2 * (size_t)L * D * FF) / 4;
            prep_weights_kernel<<<(int)((n4 + 255) / 256), 256>>>(Wo, W1, W2);
            prepped = true;
        }
        // Wo projection: narrow N -> BM=64 variant (wave quantization fix)
        gemm_fp16_bm64<<<dim3(D / 128, T / 64), 128, gk64::SMEM_BYTES>>>(
            po, pwo + (size_t)l * D * D, px, bo + (size_t)l * D, px, T, D, D);
        ln_half_kernel<<<T, 256>>>(px, ph, ln2_g + (size_t)l * D, ln2_b + (size_t)l * D);
        gemm_fp16<2, __half><<<dim3(FF / 128, T / 128), 128, gk::SMEM_BYTES>>>(
            ph, pw1 + (size_t)l * D * FF, pf, b1 + (size_t)l * FF, nullptr, T, FF, D);
        // W2 projection: narrow N -> BM=64 variant
        gemm_fp16_bm64<<<dim3(D / 128, T / 64), 128, gk64::SMEM_BYTES>>>(
            pf, pw2 + (size_t)l * FF * D, px, b2 + (size_t)l * D, px, T, D, FF);
    }

    ln_float_kernel<<<T, 256>>>(px, out, lnf_g, lnf_b);
}

// round 16
// speedup vs baseline: 1.0182x; 1.0077x over previous
#include <cuda_runtime.h>
#include <mma.h>
#include <cuda_fp16.h>
#include <cstdint>
#include <cstddef>

using namespace nvcuda;

namespace cfg {
constexpr int B = 16, S = 512, D = 768, H = 12, DH = 64, L = 12, FF = 3072, V = 30522;
constexpr int T = B * S;          // 8192 tokens
constexpr int QN = 3 * D;         // 2304 (q|k|v packed)
}

// -------------------- scratch (static device memory; no allocs) --------------------
__device__ float  g_x[(size_t)cfg::T * cfg::D];              // residual (fp32)
__device__ __half g_h[(size_t)cfg::T * cfg::D];              // LN out (half)
__device__ __half g_qkv[(size_t)cfg::T * cfg::QN];           // q|k|v (half)
__device__ __half g_o[(size_t)cfg::T * cfg::D];              // attn out (half)
__device__ __half g_ff[(size_t)cfg::T * cfg::FF];            // FFN hidden (half)
__device__ __half g_wqkv[(size_t)cfg::L * cfg::D * cfg::QN]; // packed qkv W (half)
__device__ __half g_wo[(size_t)cfg::L * cfg::D * cfg::D];
__device__ __half g_w1[(size_t)cfg::L * cfg::D * cfg::FF];
__device__ __half g_w2[(size_t)cfg::L * cfg::FF * cfg::D];
__device__ int g_idx64;

// -------------------- warp reduction --------------------
__device__ __forceinline__ float warp_sum(float v) {
#pragma unroll
    for (int o = 16; o; o >>= 1) v += __shfl_xor_sync(0xffffffffu, v, o);
    return v;
}

// -------------------- idx dtype probe --------------------
__global__ void detect_idx_kernel(const void* p) {
    const long long* q = (const long long*)p;
    __shared__ int sbad;
    if (threadIdx.x == 0) sbad = 0;
    __syncthreads();
    int bad = 0;
    for (int i = threadIdx.x; i < 4096; i += 256) {
        long long v = q[i];
        if (v < 0 || v >= (long long)cfg::V) bad = 1;
    }
    if (bad) atomicOr(&sbad, 1);
    __syncthreads();
    if (threadIdx.x == 0) g_idx64 = sbad ? 0 : 1;
}

// -------------------- weight repack: (L,H,D,DH)x3 -> (L, D, 2304) half -------------
__global__ void repack_kernel(const float* __restrict__ Wq,
                              const float* __restrict__ Wk,
                              const float* __restrict__ Wv) {
    size_t i = (size_t)blockIdx.x * blockDim.x + threadIdx.x;
    size_t total = (size_t)cfg::L * cfg::D * cfg::QN;
    if (i >= total) return;
    int j = (int)(i % cfg::QN);
    size_t ld = i / cfg::QN;
    int d = (int)(ld % cfg::D);
    int l = (int)(ld / cfg::D);
    const float* W;
    int jj = j;
    if (j < cfg::D) { W = Wq; }
    else if (j < 2 * cfg::D) { W = Wk; jj = j - cfg::D; }
    else { W = Wv; jj = j - 2 * cfg::D; }
    int h = jj / cfg::DH, k = jj % cfg::DH;
    g_wqkv[i] = __float2half_rn(W[((((size_t)l * cfg::H + h) * cfg::D) + d) * cfg::DH + k]);
}

// -------------------- merged half convert of Wo, W1, W2 --------------------
__global__ void prep_weights_kernel(const float* __restrict__ Wo,
                                    const float* __restrict__ W1,
                                    const float* __restrict__ W2) {
    using namespace cfg;
    constexpr size_t N1 = (size_t)L * D * D / 4;
    constexpr size_t N2 = N1 + (size_t)L * D * FF / 4;
    constexpr size_t N3 = N2 + (size_t)L * FF * D / 4;
    size_t i = (size_t)blockIdx.x * blockDim.x + threadIdx.x;
    if (i >= N3) return;
    const float4* src;
    __half* dst;
    size_t off;
    if (i < N1)      { src = (const float4*)Wo; dst = g_wo; off = i; }
    else if (i < N2) { src = (const float4*)W1; dst = g_w1; off = i - N1; }
    else             { src = (const float4*)W2; dst = g_w2; off = i - N2; }
    float4 v = src[off];
    __half2 h0 = __floats2half2_rn(v.x, v.y);
    __half2 h1 = __floats2half2_rn(v.z, v.w);
    uint2 u;
    u.x = reinterpret_cast<uint32_t&>(h0);
    u.y = reinterpret_cast<uint32_t&>(h1);
    *reinterpret_cast<uint2*>(dst + off * 4) = u;
}

// -------------------- fused embedding + LN_emb + LN1(layer0), warp per token -------
// grid T/8, 256 threads (8 warps). Each thread owns 24 cols (6 float4 chunks).
__global__ void embed_ln_ln1_kernel(const void* __restrict__ idxp,
                                    const float* __restrict__ tok,
                                    const float* __restrict__ seg,
                                    const float* __restrict__ pos,
                                    const float* __restrict__ ge, const float* __restrict__ be,
                                    const float* __restrict__ g1, const float* __restrict__ b1) {
    const int lane = threadIdx.x & 31;
    const int t = blockIdx.x * 8 + (threadIdx.x >> 5);
    const int s = t % cfg::S;
    long long id;
    if (g_idx64) id = ((const long long*)idxp)[t];
    else         id = (long long)((const int*)idxp)[t];
    int sg = (s >= cfg::S / 2 + 1) ? 1 : 0;

    const float4* tk = (const float4*)(tok + (size_t)id * cfg::D);
    const float4* se = (const float4*)(seg + (size_t)sg * cfg::D);
    const float4* po = (const float4*)(pos + (size_t)s * cfg::D);
    float v[24];
    float tot = 0.f;
#pragma unroll
    for (int i = 0; i < 6; i++) {
        int f = lane + i * 32;
        float4 a = tk[f], b4 = se[f], c4 = po[f];
        v[i * 4 + 0] = a.x + b4.x + c4.x;
        v[i * 4 + 1] = a.y + b4.y + c4.y;
        v[i * 4 + 2] = a.z + b4.z + c4.z;
        v[i * 4 + 3] = a.w + b4.w + c4.w;
        tot += v[i * 4] + v[i * 4 + 1] + v[i * 4 + 2] + v[i * 4 + 3];
    }
    float mean = warp_sum(tot) * (1.f / cfg::D);
    float q = 0.f;
#pragma unroll
    for (int i = 0; i < 24; i++) { float d = v[i] - mean; q += d * d; }
    float inv = rsqrtf(warp_sum(q) * (1.f / cfg::D) + 1e-5f);

    float x[24];
    float tot2 = 0.f;
    float4* xout = (float4*)(g_x + (size_t)t * cfg::D);
#pragma unroll
    for (int i = 0; i < 6; i++) {
        int f = lane + i * 32;
        float4 w;
#pragma unroll
        for (int u = 0; u < 4; u++) {
            int c = f * 4 + u;
            x[i * 4 + u] = (v[i * 4 + u] - mean) * inv * ge[c] + be[c];
            tot2 += x[i * 4 + u];
        }
        w.x = x[i * 4]; w.y = x[i * 4 + 1]; w.z = x[i * 4 + 2]; w.w = x[i * 4 + 3];
        xout[f] = w;
    }
    // LN1 (layer 0) -> g_h (half)
    float mean2 = warp_sum(tot2) * (1.f / cfg::D);
    float q2 = 0.f;
#pragma unroll
    for (int i = 0; i < 24; i++) { float d = x[i] - mean2; q2 += d * d; }
    float inv2 = rsqrtf(warp_sum(q2) * (1.f / cfg::D) + 1e-5f);
    __half* hrow = g_h + (size_t)t * cfg::D;
#pragma unroll
    for (int i = 0; i < 6; i++) {
        int f = lane + i * 32;
        float o0 = (x[i * 4 + 0] - mean2) * inv2 * g1[f * 4 + 0] + b1[f * 4 + 0];
        float o1 = (x[i * 4 + 1] - mean2) * inv2 * g1[f * 4 + 1] + b1[f * 4 + 1];
        float o2 = (x[i * 4 + 2] - mean2) * inv2 * g1[f * 4 + 2] + b1[f * 4 + 2];
        float o3 = (x[i * 4 + 3] - mean2) * inv2 * g1[f * 4 + 3] + b1[f * 4 + 3];
        __half2 h0 = __floats2half2_rn(o0, o1);
        __half2 h1 = __floats2half2_rn(o2, o3);
        uint2 u;
        u.x = reinterpret_cast<uint32_t&>(h0);
        u.y = reinterpret_cast<uint32_t&>(h1);
        *reinterpret_cast<uint2*>(hrow + f * 4) = u;
    }
}

// -------------------- LayerNorm to half, warp per token --------------------
__global__ void ln_half_kernel(const float* __restrict__ src, __half* __restrict__ dst,
                               const float* __restrict__ g, const float* __restrict__ b) {
    const int lane = threadIdx.x & 31;
    const int t = blockIdx.x * 8 + (threadIdx.x >> 5);
    const float4* x4 = (const float4*)(src + (size_t)t * cfg::D);
    float v[24];
    float tot = 0.f;
#pragma unroll
    for (int i = 0; i < 6; i++) {
        float4 a = x4[lane + i * 32];
        v[i * 4 + 0] = a.x; v[i * 4 + 1] = a.y; v[i * 4 + 2] = a.z; v[i * 4 + 3] = a.w;
        tot += a.x + a.y + a.z + a.w;
    }
    float mean = warp_sum(tot) * (1.f / cfg::D);
    float q = 0.f;
#pragma unroll
    for (int i = 0; i < 24; i++) { float d = v[i] - mean; q += d * d; }
    float inv = rsqrtf(warp_sum(q) * (1.f / cfg::D) + 1e-5f);
    __half* drow = dst + (size_t)t * cfg::D;
#pragma unroll
    for (int i = 0; i < 6; i++) {
        int f = lane + i * 32;
        float o0 = (v[i * 4 + 0] - mean) * inv * g[f * 4 + 0] + b[f * 4 + 0];
        float o1 = (v[i * 4 + 1] - mean) * inv * g[f * 4 + 1] + b[f * 4 + 1];
        float o2 = (v[i * 4 + 2] - mean) * inv * g[f * 4 + 2] + b[f * 4 + 2];
        float o3 = (v[i * 4 + 3] - mean) * inv * g[f * 4 + 3] + b[f * 4 + 3];
        __half2 h0 = __floats2half2_rn(o0, o1);
        __half2 h1 = __floats2half2_rn(o2, o3);
        uint2 u;
        u.x = reinterpret_cast<uint32_t&>(h0);
        u.y = reinterpret_cast<uint32_t&>(h1);
        *reinterpret_cast<uint2*>(drow + f * 4) = u;
    }
}

// -------------------- final LayerNorm to fp32, warp per token --------------------
__global__ void ln_float_kernel(const float* __restrict__ src, float* __restrict__ dst,
                                const float* __restrict__ g, const float* __restrict__ b) {
    const int lane = threadIdx.x & 31;
    const int t = blockIdx.x * 8 + (threadIdx.x >> 5);
    const float4* x4 = (const float4*)(src + (size_t)t * cfg::D);
    float v[24];
    float tot = 0.f;
#pragma unroll
    for (int i = 0; i < 6; i++) {
        float4 a = x4[lane + i * 32];
        v[i * 4 + 0] = a.x; v[i * 4 + 1] = a.y; v[i * 4 + 2] = a.z; v[i * 4 + 3] = a.w;
        tot += a.x + a.y + a.z + a.w;
    }
    float mean = warp_sum(tot) * (1.f / cfg::D);
    float q = 0.f;
#pragma unroll
    for (int i = 0; i < 24; i++) { float d = v[i] - mean; q += d * d; }
    float inv = rsqrtf(warp_sum(q) * (1.f / cfg::D) + 1e-5f);
    float4* drow = (float4*)(dst + (size_t)t * cfg::D);
#pragma unroll
    for (int i = 0; i < 6; i++) {
        int f = lane + i * 32;
        float4 w;
        w.x = (v[i * 4 + 0] - mean) * inv * g[f * 4 + 0] + b[f * 4 + 0];
        w.y = (v[i * 4 + 1] - mean) * inv * g[f * 4 + 1] + b[f * 4 + 1];
        w.z = (v[i * 4 + 2] - mean) * inv * g[f * 4 + 2] + b[f * 4 + 2];
        w.w = (v[i * 4 + 3] - mean) * inv * g[f * 4 + 3] + b[f * 4 + 3];
        drow[f] = w;
    }
}

// -------------------- cp.async helpers --------------------
__device__ __forceinline__ void cpasync16(void* smem, const void* gmem) {
    uint32_t s = (uint32_t)__cvta_generic_to_shared(smem);
    asm volatile("cp.async.cg.shared.global [%0], [%1], 16;\n" :: "r"(s), "l"(gmem));
}
__device__ __forceinline__ void cp_commit() {
    asm volatile("cp.async.commit_group;\n");
}

// -------------------- pipelined fp16 WMMA GEMM, warp tile 64x64, BK=64 -------------
// (R13 configuration — best measured; mainloop frozen)
// C[M,N] = A[M,K] @ B[K,N]; A,B half row-major; accum fp32.
// 128 threads (2x2 warps), block 128x128, BK=64, 2-stage cp.async pipeline.
// EPI: 0 = store half, 1 = float C = res + AB + bias, 2 = half C = relu(AB + bias)
namespace gk {
constexpr int BM = 128, BN = 128, BK = 64;
constexpr int ASTR = 72;                   // halfs (64 + 8 pad)
constexpr int BSTR = 136;                  // halfs (128 + 8 pad)
constexpr int A_TILE = BM * ASTR;          // 9216 halfs
constexpr int B_TILE = BK * BSTR;          // 8704 halfs
constexpr int STAGE_H = A_TILE + B_TILE;   // 17920 halfs (35840 B)
constexpr int ESTR = 132;                  // fp32 epilogue stride
constexpr int SMEM_BYTES = 2 * STAGE_H * 2; // 71680 (covers epilogue 67584)
}

template <int EPI, typename OutT>
__global__ __launch_bounds__(128, 2)
void gemm_fp16(const __half* __restrict__ A, const __half* __restrict__ B,
               OutT* __restrict__ C, const float* __restrict__ bias,
               const float* __restrict__ res, int M, int N, int K) {
    using namespace gk;
    extern __shared__ char smc[];
    __half* sm = reinterpret_cast<__half*>(smc);

    const int tid = threadIdx.x, warp = tid >> 5;
    const int wy = warp >> 1, wx = warp & 1;     // 2x2 warps, warp tile 64x64
    const int bm = blockIdx.y * BM, bn = blockIdx.x * BN;

    wmma::fragment<wmma::accumulator, 16, 16, 16, float> acc[4][4];
#pragma unroll
    for (int i = 0; i < 4; i++)
#pragma unroll
        for (int j = 0; j < 4; j++) wmma::fill_fragment(acc[i][j], 0.f);

    auto load_tiles = [&](int st, int kt) {
        __half* dstA = sm + st * STAGE_H;
        const __half* srcA = A + (size_t)bm * K + kt * BK;
#pragma unroll
        for (int i = 0; i < 8; i++) {                 // 128 rows x 8 chunks of 8 halfs
            int id = tid + i * 128;
            int r = id >> 3, c = (id & 7) * 8;
            cpasync16(&dstA[r * ASTR + c], &srcA[(size_t)r * K + c]);
        }
        __half* dstB = sm + st * STAGE_H + A_TILE;
        const __half* srcB = B + (size_t)(kt * BK) * N + bn;
#pragma unroll
        for (int i = 0; i < 8; i++) {                 // 64 rows x 16 chunks
            int id = tid + i * 128;
            int r = id >> 4, c = (id & 15) * 8;
            cpasync16(&dstB[r * BSTR + c], &srcB[(size_t)r * N + c]);
        }
    };

    const int nk = K / BK;
    load_tiles(0, 0); cp_commit();

    for (int kt = 0; kt < nk; kt++) {
        asm volatile("cp.async.wait_group 0;\n");
        __syncthreads();
        if (kt + 1 < nk) { load_tiles((kt + 1) & 1, kt + 1); cp_commit(); }

        const __half* a = sm + (kt & 1) * STAGE_H;
        const __half* b = a + A_TILE;
#pragma unroll
        for (int kk = 0; kk < BK; kk += 16) {
            wmma::fragment<wmma::matrix_a, 16, 16, 16, __half, wmma::row_major> af[4];
            wmma::fragment<wmma::matrix_b, 16, 16, 16, __half, wmma::row_major> bf[4];
#pragma unroll
            for (int i = 0; i < 4; i++)
                wmma::load_matrix_sync(af[i], a + (wy * 64 + i * 16) * ASTR + kk, ASTR);
#pragma unroll
            for (int j = 0; j < 4; j++)
                wmma::load_matrix_sync(bf[j], b + kk * BSTR + wx * 64 + j * 16, BSTR);
#pragma unroll
            for (int i = 0; i < 4; i++)
#pragma unroll
                for (int j = 0; j < 4; j++)
                    wmma::mma_sync(acc[i][j], af[i], bf[j], acc[i][j]);
        }
        __syncthreads();
    }

    // epilogue: stage fp32 128x128 in smem, fused write
    float* epi = reinterpret_cast<float*>(smc);
#pragma unroll
    for (int i = 0; i < 4; i++)
#pragma unroll
        for (int j = 0; j < 4; j++)
            wmma::store_matrix_sync(epi + (wy * 64 + i * 16) * ESTR + wx * 64 + j * 16,
                                    acc[i][j], ESTR, wmma::mem_row_major);
    __syncthreads();
#pragma unroll
    for (int it = 0; it < 32; it++) {
        int id = tid + it * 128;
        int r = id >> 5, c4 = (id & 31) * 4;
        float4 v = *reinterpret_cast<float4*>(&epi[r * ESTR + c4]);
        int gc = bn + c4;
        size_t gi = (size_t)(bm + r) * N + gc;
        if (EPI == 1) {
            float4 rv = *reinterpret_cast<const float4*>(&res[gi]);
            float4 bv = *reinterpret_cast<const float4*>(&bias[gc]);
            v.x += rv.x + bv.x; v.y += rv.y + bv.y; v.z += rv.z + bv.z; v.w += rv.w + bv.w;
            *reinterpret_cast<float4*>(&((float*)C)[gi]) = v;
        } else {
            if (EPI == 2) {
                float4 bv = *reinterpret_cast<const float4*>(&bias[gc]);
                v.x = fmaxf(v.x + bv.x, 0.f); v.y = fmaxf(v.y + bv.y, 0.f);
                v.z = fmaxf(v.z + bv.z, 0.f); v.w = fmaxf(v.w + bv.w, 0.f);
            }
            __half2 h0 = __floats2half2_rn(v.x, v.y);
            __half2 h1 = __floats2half2_rn(v.z, v.w);
            uint2 u;
            u.x = reinterpret_cast<uint32_t&>(h0);
            u.y = reinterpret_cast<uint32_t&>(h1);
            *reinterpret_cast<uint2*>(&((__half*)C)[gi]) = u;
        }
    }
}

// -------------------- fp16 WMMA flash attention, register O accumulator ------------
// grid (S/64, H, B), 256 threads (8 warps as 4x2; warp tile 16x32).
namespace ak {
constexpr int STRH = 72;                       // half tile stride
constexpr int STRF = 68;                       // fp32 stride
constexpr int TILEB = 64 * STRH * 2;           // 9216 B per half tile
constexpr int QH_OFF = 0;
constexpr int KH_OFF = QH_OFF + TILEB;         // K0, K1
constexpr int VH_OFF = KH_OFF + 2 * TILEB;     // V0, V1
constexpr int PH_OFF = VH_OFF + 2 * TILEB;     // half P tile
constexpr int SF_OFF = PH_OFF + TILEB;         // fp32 scores / PV result (reused)
constexpr int SMEM_BYTES = SF_OFF + 64 * STRF * 4;  // 72704
}

__global__ __launch_bounds__(256)
void attn_kernel() {
    using namespace ak;
    extern __shared__ char smc[];
    __half* Qs = reinterpret_cast<__half*>(smc + QH_OFF);
    __half* Ph = reinterpret_cast<__half*>(smc + PH_OFF);
    float*  Sf = reinterpret_cast<float*>(smc + SF_OFF);

    const int qb = blockIdx.x, h = blockIdx.y, b = blockIdx.z;
    const int tid = threadIdx.x, warp = tid >> 5;
    const int wy = warp >> 1, wx = warp & 1;
    const int r = tid >> 2, q4 = tid & 3;
    const size_t tokbase = (size_t)b * cfg::S;

    auto load_kv = [&](int st, int ck) {
        __half* Kd = reinterpret_cast<__half*>(smc + KH_OFF + st * TILEB);
        __half* Vd = reinterpret_cast<__half*>(smc + VH_OFF + st * TILEB);
#pragma unroll
        for (int i = 0; i < 2; i++) {
            int id = tid + i * 256;                  // 512 chunks of 8 halfs
            int rr = id >> 3, cc = (id & 7) * 8;
            size_t base = (tokbase + ck * 64 + rr) * cfg::QN + h * cfg::DH + cc;
            cpasync16(&Kd[rr * STRH + cc], &g_qkv[base + cfg::D]);
            cpasync16(&Vd[rr * STRH + cc], &g_qkv[base + 2 * cfg::D]);
        }
    };
    load_kv(0, 0); cp_commit();

    // load Q (scale by 0.125 — exact in fp16)
    const __half2 sc2 = __floats2half2_rn(0.125f, 0.125f);
#pragma unroll
    for (int i = 0; i < 2; i++) {
        int id = tid + i * 256;
        int rr = id >> 3, cc = (id & 7) * 8;
        const __half2* src = reinterpret_cast<const __half2*>(
            &g_qkv[(tokbase + qb * 64 + rr) * cfg::QN + h * cfg::DH + cc]);
        __half2* dst = reinterpret_cast<__half2*>(&Qs[rr * STRH + cc]);
#pragma unroll
        for (int u = 0; u < 4; u++) dst[u] = __hmul2(src[u], sc2);
    }
    __syncthreads();

    wmma::fragment<wmma::matrix_a, 16, 16, 16, __half, wmma::row_major> qf[4];
#pragma unroll
    for (int k16 = 0; k16 < 4; k16++)
        wmma::load_matrix_sync(qf[k16], Qs + (wy * 16) * STRH + k16 * 16, STRH);

    float m_r = -1e30f, l_r = 0.f;
    float O[16];
#pragma unroll
    for (int c = 0; c < 16; c++) O[c] = 0.f;

    for (int ck = 0; ck < cfg::S / 64; ck++) {
        asm volatile("cp.async.wait_group 0;\n");
        __syncthreads();   // KV ready; also protects Sf reuse from prev accumulate
        if (ck + 1 < cfg::S / 64) { load_kv((ck + 1) & 1, ck + 1); cp_commit(); }
        const __half* Ks = reinterpret_cast<const __half*>(smc + KH_OFF + (ck & 1) * TILEB);
        const __half* Vs = reinterpret_cast<const __half*>(smc + VH_OFF + (ck & 1) * TILEB);

        // scores: S = Q @ K^T
        {
            wmma::fragment<wmma::accumulator, 16, 16, 16, float> sf[2];
            wmma::fill_fragment(sf[0], 0.f);
            wmma::fill_fragment(sf[1], 0.f);
#pragma unroll
            for (int k16 = 0; k16 < 4; k16++) {
#pragma unroll
                for (int j = 0; j < 2; j++) {
                    wmma::fragment<wmma::matrix_b, 16, 16, 16, __half, wmma::col_major> bf;
                    wmma::load_matrix_sync(bf, Ks + (wx * 32 + j * 16) * STRH + k16 * 16, STRH);
                    wmma::mma_sync(sf[j], qf[k16], bf, sf[j]);
                }
            }
#pragma unroll
            for (int j = 0; j < 2; j++)
                wmma::store_matrix_sync(Sf + (wy * 16) * STRF + wx * 32 + j * 16, sf[j],
                                        STRF, wmma::mem_row_major);
        }
        __syncthreads();

        // scalar online softmax: 4 threads per row, 16 cols each; O scaled in regs
        {
            float s[16];
            float rmax = -1e30f;
#pragma unroll
            for (int c = 0; c < 16; c++) {
                s[c] = Sf[r * STRF + q4 * 16 + c];
                rmax = fmaxf(rmax, s[c]);
            }
            rmax = fmaxf(rmax, __shfl_xor_sync(0xffffffffu, rmax, 1));
            rmax = fmaxf(rmax, __shfl_xor_sync(0xffffffffu, rmax, 2));
            float mnew = fmaxf(m_r, rmax);
            float scale = __expf(m_r - mnew);
            float rs = 0.f;
#pragma unroll
            for (int c = 0; c < 16; c++) {
                float p = __expf(s[c] - mnew);
                Ph[r * STRH + q4 * 16 + c] = __float2half_rn(p);
                rs += p;
            }
            rs += __shfl_xor_sync(0xffffffffu, rs, 1);
            rs += __shfl_xor_sync(0xffffffffu, rs, 2);
            l_r = l_r * scale + rs;
            m_r = mnew;
#pragma unroll
            for (int c = 0; c < 16; c++) O[c] *= scale;
        }
        __syncthreads();   // Ph complete; all warps done reading Sf

        // O_chunk = P @ V  (result into Sf, reused)
        {
            wmma::fragment<wmma::accumulator, 16, 16, 16, float> of[2];
            wmma::fill_fragment(of[0], 0.f);
            wmma::fill_fragment(of[1], 0.f);
#pragma unroll
            for (int k16 = 0; k16 < 4; k16++) {
                wmma::fragment<wmma::matrix_a, 16, 16, 16, __half, wmma::row_major> pf;
                wmma::load_matrix_sync(pf, Ph + (wy * 16) * STRH + k16 * 16, STRH);
#pragma unroll
                for (int j = 0; j < 2; j++) {
                    wmma::fragment<wmma::matrix_b, 16, 16, 16, __half, wmma::row_major> vf;
                    wmma::load_matrix_sync(vf, Vs + (k16 * 16) * STRH + wx * 32 + j * 16, STRH);
                    wmma::mma_sync(of[j], pf, vf, of[j]);
                }
            }
#pragma unroll
            for (int j = 0; j < 2; j++)
                wmma::store_matrix_sync(Sf + (wy * 16) * STRF + wx * 32 + j * 16, of[j],
                                        STRF, wmma::mem_row_major);
        }
        __syncthreads();

        // accumulate chunk into register O (next top-of-loop sync protects Sf)
#pragma unroll
        for (int c = 0; c < 16; c++)
            O[c] += Sf[r * STRF + q4 * 16 + c];
    }

    // normalize + write half output
    {
        float inv = 1.f / l_r;
        __half* orow = &g_o[(tokbase + qb * 64 + r) * cfg::D + h * cfg::DH + q4 * 16];
#pragma unroll
        for (int cc = 0; cc < 4; cc++) {
            __half2 h0 = __floats2half2_rn(O[cc * 4 + 0] * inv, O[cc * 4 + 1] * inv);
            __half2 h1 = __floats2half2_rn(O[cc * 4 + 2] * inv, O[cc * 4 + 3] * inv);
            uint2 u;
            u.x = reinterpret_cast<uint32_t&>(h0);
            u.y = reinterpret_cast<uint32_t&>(h1);
            *reinterpret_cast<uint2*>(&orow[cc * 4]) = u;
        }
    }
}

// -------------------- host launcher --------------------
extern "C" void kernel_launch(void* const* d_in, const int* in_sizes, int n_in,
                              void* d_out, int out_size) {
    using namespace cfg;
    const void*  idx      = d_in[0];
    const float* tok_emb  = (const float*)d_in[1];
    const float* seg_emb  = (const float*)d_in[2];
    const float* pos_emb  = (const float*)d_in[3];
    const float* ln_emb_g = (const float*)d_in[4];
    const float* ln_emb_b = (const float*)d_in[5];
    const float* Wq       = (const float*)d_in[6];
    const float* Wk       = (const float*)d_in[7];
    const float* Wv       = (const float*)d_in[8];
    const float* Wo       = (const float*)d_in[9];
    const float* bo       = (const float*)d_in[10];
    const float* ln1_g    = (const float*)d_in[11];
    const float* ln1_b    = (const float*)d_in[12];
    const float* ln2_g    = (const float*)d_in[13];
    const float* ln2_b    = (const float*)d_in[14];
    const float* W1       = (const float*)d_in[15];
    const float* b1       = (const float*)d_in[16];
    const float* W2       = (const float*)d_in[17];
    const float* b2       = (const float*)d_in[18];
    const float* lnf_g    = (const float*)d_in[19];
    const float* lnf_b    = (const float*)d_in[20];
    float* out = (float*)d_out;

    float *px;
    __half *ph, *pq, *po, *pf, *pwq, *pwo, *pw1, *pw2;
    cudaGetSymbolAddress((void**)&px, g_x);
    cudaGetSymbolAddress((void**)&ph, g_h);
    cudaGetSymbolAddress((void**)&pq, g_qkv);
    cudaGetSymbolAddress((void**)&po, g_o);
    cudaGetSymbolAddress((void**)&pf, g_ff);
    cudaGetSymbolAddress((void**)&pwq, g_wqkv);
    cudaGetSymbolAddress((void**)&pwo, g_wo);
    cudaGetSymbolAddress((void**)&pw1, g_w1);
    cudaGetSymbolAddress((void**)&pw2, g_w2);

    cudaFuncSetAttribute((const void*)gemm_fp16<0, __half>, cudaFuncAttributeMaxDynamicSharedMemorySize, gk::SMEM_BYTES);
    cudaFuncSetAttribute((const void*)gemm_fp16<1, float>,  cudaFuncAttributeMaxDynamicSharedMemorySize, gk::SMEM_BYTES);
    cudaFuncSetAttribute((const void*)gemm_fp16<2, __half>, cudaFuncAttributeMaxDynamicSharedMemorySize, gk::SMEM_BYTES);
    cudaFuncSetAttribute((const void*)attn_kernel, cudaFuncAttributeMaxDynamicSharedMemorySize, ak::SMEM_BYTES);

    // launches 1-3: prep; launch #4 = QKV GEMM (ncu capture slot)
    detect_idx_kernel<<<1, 256>>>(idx);
    {
        size_t total = (size_t)L * D * QN;
        repack_kernel<<<(int)((total + 255) / 256), 256>>>(Wq, Wk, Wv);
    }
    embed_ln_ln1_kernel<<<T / 8, 256>>>(idx, tok_emb, seg_emb, pos_emb,
                                        ln_emb_g, ln_emb_b, ln1_g, ln1_b);

    bool prepped = false;
    for (int l = 0; l < L; l++) {
        if (l > 0)
            ln_half_kernel<<<T / 8, 256>>>(px, ph, ln1_g + (size_t)l * D, ln1_b + (size_t)l * D);
        gemm_fp16<0, __half><<<dim3(QN / 128, T / 128), 128, gk::SMEM_BYTES>>>(
            ph, pwq + (size_t)l * D * QN, pq, nullptr, nullptr, T, QN, D);
        attn_kernel<<<dim3(S / 64, H, B), 256, ak::SMEM_BYTES>>>();
        if (!prepped) {
            size_t n4 = ((size_t)L * D * D + 2 * (size_t)L * D * FF) / 4;
            prep_weights_kernel<<<(int)((n4 + 255) / 256), 256>>>(Wo, W1, W2);
            prepped = true;
        }
        gemm_fp16<1, float><<<dim3(D / 128, T / 128), 128, gk::SMEM_BYTES>>>(
            po, pwo + (size_t)l * D * D, px, bo + (size_t)l * D, px, T, D, D);
        ln_half_kernel<<<T / 8, 256>>>(px, ph, ln2_g + (size_t)l * D, ln2_b + (size_t)l * D);
        gemm_fp16<2, __half><<<dim3(FF / 128, T / 128), 128, gk::SMEM_BYTES>>>(
            ph, pw1 + (size_t)l * D * FF, pf, b1 + (size_t)l * FF, nullptr, T, FF, D);
        gemm_fp16<1, float><<<dim3(D / 128, T / 128), 128, gk::SMEM_BYTES>>>(
            pf, pw2 + (size_t)l * FF * D, px, b2 + (size_t)l * D, px, T, D, FF);
    }

    ln_float_kernel<<<T / 8, 256>>>(px, out, lnf_g, lnf_b);
}